// round 2
// baseline (speedup 1.0000x reference)
#include <cuda_runtime.h>
#include <cstdint>

// Problem constants
#define BB 8
#define NN 2048
#define TT 12
#define DD 256
#define HH 8
#define DKK 32
#define MM 8

#define ROWS (BB*NN*TT)     // 196608
#define BNTOT (BB*NN)       // 16384

// Scratch (device globals: allocation-free kernel_launch)
__device__ float g_qkv[(size_t)ROWS * 768];   // [row][0:256)=Q [256:512)=K [512:768)=V
__device__ float g_att[(size_t)ROWS * 256];   // merged attention output
__device__ float g_fc [(size_t)ROWS * 256];   // fc output (pre-residual)

// ---------------------------------------------------------------------------
// GEMM: C[M x N] = A[M x 256] @ W^T + bias,  W row-major [n][k] (k contiguous)
// Tiles: BM=128, BN=128, BK=16; 256 threads; 8x8 microtiles.
// N-tile selects one of up to 3 weight matrices (QKV fused launch).
// ---------------------------------------------------------------------------
#define BM 128
#define BNT 128
#define BK 16

__global__ __launch_bounds__(256) void gemm_nt(
    const float* __restrict__ A,
    const float* __restrict__ W0, const float* __restrict__ W1, const float* __restrict__ W2,
    const float* __restrict__ b0, const float* __restrict__ b1, const float* __restrict__ b2,
    float* __restrict__ C, int ldc)
{
    __shared__ float As[BK][BM + 4];
    __shared__ float Bs[BK][BNT + 4];

    const int tid = threadIdx.x;
    const int m0  = blockIdx.y * BM;
    const int n0  = blockIdx.x * BNT;
    const int mat = n0 >> 8;                     // which weight matrix
    const float* W    = (mat == 0) ? W0 : (mat == 1 ? W1 : W2);
    const float* bias = (mat == 0) ? b0 : (mat == 1 ? b1 : b2);
    const int nw = n0 & 255;                     // column base inside matrix

    const int ty = tid >> 4;                     // 0..15
    const int tx = tid & 15;                     // 0..15
    const int lr = tid >> 2;                     // 0..63 loader row
    const int lc = (tid & 3) << 2;               // 0,4,8,12 loader col

    float acc[8][8];
    #pragma unroll
    for (int i = 0; i < 8; i++)
        #pragma unroll
        for (int j = 0; j < 8; j++) acc[i][j] = 0.f;

    for (int k0 = 0; k0 < 256; k0 += BK) {
        #pragma unroll
        for (int hh = 0; hh < 2; hh++) {
            int r = lr + hh * 64;
            float4 a4 = *(const float4*)(A + (size_t)(m0 + r) * 256 + (k0 + lc));
            As[lc + 0][r] = a4.x; As[lc + 1][r] = a4.y;
            As[lc + 2][r] = a4.z; As[lc + 3][r] = a4.w;
            float4 w4 = *(const float4*)(W + (size_t)(nw + r) * 256 + (k0 + lc));
            Bs[lc + 0][r] = w4.x; Bs[lc + 1][r] = w4.y;
            Bs[lc + 2][r] = w4.z; Bs[lc + 3][r] = w4.w;
        }
        __syncthreads();

        #pragma unroll
        for (int k = 0; k < BK; k++) {
            float a[8], b[8];
            *(float4*)(a    ) = *(const float4*)&As[k][ty * 8];
            *(float4*)(a + 4) = *(const float4*)&As[k][ty * 8 + 4];
            *(float4*)(b    ) = *(const float4*)&Bs[k][tx * 8];
            *(float4*)(b + 4) = *(const float4*)&Bs[k][tx * 8 + 4];
            #pragma unroll
            for (int i = 0; i < 8; i++)
                #pragma unroll
                for (int j = 0; j < 8; j++)
                    acc[i][j] = fmaf(a[i], b[j], acc[i][j]);
        }
        __syncthreads();
    }

    float bv[8];
    #pragma unroll
    for (int j = 0; j < 8; j++) bv[j] = bias[nw + tx * 8 + j];

    #pragma unroll
    for (int i = 0; i < 8; i++) {
        int row = m0 + ty * 8 + i;
        float4 o1 = make_float4(acc[i][0] + bv[0], acc[i][1] + bv[1],
                                acc[i][2] + bv[2], acc[i][3] + bv[3]);
        float4 o2 = make_float4(acc[i][4] + bv[4], acc[i][5] + bv[5],
                                acc[i][6] + bv[6], acc[i][7] + bv[7]);
        *(float4*)(C + (size_t)row * ldc + n0 + tx * 8    ) = o1;
        *(float4*)(C + (size_t)row * ldc + n0 + tx * 8 + 4) = o2;
    }
}

// ---------------------------------------------------------------------------
// Attention: one block per (b,n); warp w = head w.
// Causal T=12 softmax attention + M=8 memory-bank attention, sigmoid-gated.
// ---------------------------------------------------------------------------
__global__ __launch_bounds__(256) void attn_kernel(
    const float* __restrict__ memk,   // [H][M][DK]
    const float* __restrict__ memv,   // [H][M][DK]
    const float* __restrict__ alpha,  // scalar
    const float* __restrict__ QKV,    // g_qkv
    float* __restrict__ O)            // g_att
{
    __shared__ float sQ[HH][TT][33];
    __shared__ float sK[HH][TT][33];
    __shared__ float sV[HH][TT][33];
    __shared__ float sS[HH][TT][13];  // time probs
    __shared__ float sL[HH][TT][8];   // long probs

    const int bn   = blockIdx.x;
    const int h    = threadIdx.x >> 5;
    const int lane = threadIdx.x & 31;
    const size_t rb = (size_t)bn * TT * 768;
    const float scale = 0.1767766952966369f;   // 1/sqrt(32)

    #pragma unroll
    for (int t = 0; t < TT; t++) {
        sQ[h][t][lane] = QKV[rb + (size_t)t * 768 +       h * 32 + lane];
        sK[h][t][lane] = QKV[rb + (size_t)t * 768 + 256 + h * 32 + lane];
        sV[h][t][lane] = QKV[rb + (size_t)t * 768 + 512 + h * 32 + lane];
    }
    __syncwarp();

    // time scores (only s <= t needed — exactly matches the -1e9 mask)
    for (int p = lane; p < 144; p += 32) {
        int t = p / 12, s = p - t * 12;
        if (s <= t) {
            float a = 0.f;
            #pragma unroll
            for (int k = 0; k < 32; k++) a += sQ[h][t][k] * sK[h][s][k];
            sS[h][t][s] = a * scale;
        }
    }
    // memory-bank scores
    for (int p = lane; p < 96; p += 32) {
        int t = p >> 3, m = p & 7;
        const float* mk = memk + ((h << 3) + m) * 32;
        float a = 0.f;
        #pragma unroll
        for (int k = 0; k < 32; k++) a += sQ[h][t][k] * mk[k];
        sL[h][t][m] = a * scale;
    }
    __syncwarp();

    // per-row softmax (lanes 0..11 each own a row t)
    if (lane < TT) {
        int t = lane;
        float mx = -1e30f;
        for (int s = 0; s <= t; s++) mx = fmaxf(mx, sS[h][t][s]);
        float sum = 0.f;
        for (int s = 0; s <= t; s++) { float e = __expf(sS[h][t][s] - mx); sS[h][t][s] = e; sum += e; }
        float inv = 1.f / sum;
        for (int s = 0; s <= t; s++) sS[h][t][s] *= inv;

        mx = -1e30f;
        #pragma unroll
        for (int m = 0; m < 8; m++) mx = fmaxf(mx, sL[h][t][m]);
        sum = 0.f;
        #pragma unroll
        for (int m = 0; m < 8; m++) { float e = __expf(sL[h][t][m] - mx); sL[h][t][m] = e; sum += e; }
        inv = 1.f / sum;
        #pragma unroll
        for (int m = 0; m < 8; m++) sL[h][t][m] *= inv;
    }
    __syncwarp();

    const float wl  = 1.f / (1.f + __expf(-alpha[0]));
    const float wt  = 1.f - wl;

    // outputs: lane = feature k within head
    #pragma unroll
    for (int t = 0; t < TT; t++) {
        float ot = 0.f;
        for (int s = 0; s <= t; s++) ot += sS[h][t][s] * sV[h][s][lane];
        float ol = 0.f;
        #pragma unroll
        for (int m = 0; m < 8; m++) ol += sL[h][t][m] * memv[((h << 3) + m) * 32 + lane];
        O[(size_t)bn * TT * 256 + (size_t)t * 256 + h * 32 + lane] = ot * wt + ol * wl;
    }
}

// ---------------------------------------------------------------------------
// Residual + LayerNorm: one warp per row of 256.
// ---------------------------------------------------------------------------
__global__ __launch_bounds__(256) void ln_kernel(
    const float* __restrict__ Y, const float* __restrict__ X,
    const float* __restrict__ gamma, const float* __restrict__ beta,
    float* __restrict__ out)
{
    int gw   = (blockIdx.x * blockDim.x + threadIdx.x) >> 5;
    int lane = threadIdx.x & 31;
    if (gw >= ROWS) return;
    size_t base = (size_t)gw * 256 + lane * 8;

    float4 y1 = *(const float4*)(Y + base);
    float4 y2 = *(const float4*)(Y + base + 4);
    float4 x1 = *(const float4*)(X + base);
    float4 x2 = *(const float4*)(X + base + 4);
    float hh[8] = { y1.x + x1.x, y1.y + x1.y, y1.z + x1.z, y1.w + x1.w,
                    y2.x + x2.x, y2.y + x2.y, y2.z + x2.z, y2.w + x2.w };

    float s = 0.f, sq = 0.f;
    #pragma unroll
    for (int i = 0; i < 8; i++) { s += hh[i]; sq += hh[i] * hh[i]; }
    #pragma unroll
    for (int off = 16; off; off >>= 1) {
        s  += __shfl_xor_sync(0xFFFFFFFFu, s,  off);
        sq += __shfl_xor_sync(0xFFFFFFFFu, sq, off);
    }
    float mu  = s * (1.f / 256.f);
    float var = sq * (1.f / 256.f) - mu * mu;
    float rs  = rsqrtf(var + 1e-5f);

    float4 g1 = *(const float4*)(gamma + lane * 8);
    float4 g2 = *(const float4*)(gamma + lane * 8 + 4);
    float4 be1 = *(const float4*)(beta + lane * 8);
    float4 be2 = *(const float4*)(beta + lane * 8 + 4);

    float4 o1 = make_float4((hh[0] - mu) * rs * g1.x + be1.x,
                            (hh[1] - mu) * rs * g1.y + be1.y,
                            (hh[2] - mu) * rs * g1.z + be1.z,
                            (hh[3] - mu) * rs * g1.w + be1.w);
    float4 o2 = make_float4((hh[4] - mu) * rs * g2.x + be2.x,
                            (hh[5] - mu) * rs * g2.y + be2.y,
                            (hh[6] - mu) * rs * g2.z + be2.z,
                            (hh[7] - mu) * rs * g2.w + be2.w);
    *(float4*)(out + base)     = o1;
    *(float4*)(out + base + 4) = o2;
}

// ---------------------------------------------------------------------------
extern "C" void kernel_launch(void* const* d_in, const int* in_sizes, int n_in,
                              void* d_out, int out_size)
{
    const float* x     = (const float*)d_in[0];
    const float* Wq    = (const float*)d_in[1];
    const float* bq    = (const float*)d_in[2];
    const float* Wk    = (const float*)d_in[3];
    const float* bk    = (const float*)d_in[4];
    const float* Wv    = (const float*)d_in[5];
    const float* bv    = (const float*)d_in[6];
    const float* memk  = (const float*)d_in[7];
    const float* memv  = (const float*)d_in[8];
    const float* fcw   = (const float*)d_in[9];
    const float* fcb   = (const float*)d_in[10];
    const float* gamma = (const float*)d_in[11];
    const float* beta  = (const float*)d_in[12];
    const float* alpha = (const float*)d_in[13];
    float* out = (float*)d_out;

    float *qkv, *att, *fc;
    cudaGetSymbolAddress((void**)&qkv, g_qkv);
    cudaGetSymbolAddress((void**)&att, g_att);
    cudaGetSymbolAddress((void**)&fc,  g_fc);

    // 1) fused QKV projection: [196608 x 768]
    {
        dim3 grid(768 / BNT, ROWS / BM);
        gemm_nt<<<grid, 256>>>(x, Wq, Wk, Wv, bq, bk, bv, qkv, 768);
    }
    // 2) attention per (b,n)
    attn_kernel<<<BNTOT, 256>>>(memk, memv, alpha, qkv, att);

    // 3) FC projection: [196608 x 256]
    {
        dim3 grid(256 / BNT, ROWS / BM);
        gemm_nt<<<grid, 256>>>(att, fcw, fcw, fcw, fcb, fcb, fcb, fc, 256);
    }
    // 4) residual + LayerNorm
    ln_kernel<<<(ROWS * 32 + 255) / 256, 256>>>(fc, x, gamma, beta, out);
}

// round 3
// speedup vs baseline: 1.8821x; 1.8821x over previous
#include <cuda_runtime.h>
#include <cuda_fp16.h>
#include <cstdint>

// Problem constants
#define BB 8
#define NN 2048
#define TT 12
#define DD 256
#define HH 8
#define DKK 32
#define MM 8

#define ROWS (BB*NN*TT)     // 196608
#define BNTOT (BB*NN)       // 16384

// Scratch (device globals: allocation-free kernel_launch)
__device__ float g_qkv[(size_t)ROWS * 768];   // [row][0:256)=Q [256:512)=K [512:768)=V
__device__ float g_att[(size_t)ROWS * 256];   // merged attention output
__device__ float g_fc [(size_t)ROWS * 256];   // fc output (pre-residual)

// ---------------------------------------------------------------------------
// Tensor-core GEMM, fp16 3-term split for near-fp32 accuracy.
// C[M x N] = A[M x 256] @ W^T + bias, W row-major [n][k].
// Block 128x128, BK=16, 256 threads, 8 warps (2m x 4n), warp tile 64x32.
// ---------------------------------------------------------------------------
#define BM 128
#define BNTILE 128
#define BKE 16      // k elements per stage
#define ASTR 24     // smem row stride in halves (conflict-free for ldmatrix)

__device__ __forceinline__ void ldsm4(uint32_t* r, const __half* p) {
    uint32_t a = (uint32_t)__cvta_generic_to_shared(p);
    asm volatile("ldmatrix.sync.aligned.m8n8.x4.shared.b16 {%0,%1,%2,%3}, [%4];"
                 : "=r"(r[0]), "=r"(r[1]), "=r"(r[2]), "=r"(r[3]) : "r"(a));
}

__device__ __forceinline__ void mma16816(float* d, const uint32_t* a, const uint32_t* b) {
    asm volatile("mma.sync.aligned.m16n8k16.row.col.f32.f16.f16.f32 "
        "{%0,%1,%2,%3}, {%4,%5,%6,%7}, {%8,%9}, {%0,%1,%2,%3};"
        : "+f"(d[0]), "+f"(d[1]), "+f"(d[2]), "+f"(d[3])
        : "r"(a[0]), "r"(a[1]), "r"(a[2]), "r"(a[3]), "r"(b[0]), "r"(b[1]));
}

__device__ __forceinline__ uint32_t packh(float x, float y) {
    __half2 h = __halves2half2(__float2half_rn(x), __float2half_rn(y));
    return *(uint32_t*)&h;
}

__global__ __launch_bounds__(256) void gemm_f16x3(
    const float* __restrict__ A,
    const float* __restrict__ W0, const float* __restrict__ W1, const float* __restrict__ W2,
    const float* __restrict__ b0p, const float* __restrict__ b1p, const float* __restrict__ b2p,
    float* __restrict__ C, int ldc)
{
    __shared__ __half sAhi[BM][ASTR], sAlo[BM][ASTR];
    __shared__ __half sBhi[BNTILE][ASTR], sBlo[BNTILE][ASTR];

    const int tid = threadIdx.x;
    const int m0  = blockIdx.y * BM;
    const int n0  = blockIdx.x * BNTILE;
    const int mat = n0 >> 8;
    const float* W    = (mat == 0) ? W0 : (mat == 1 ? W1 : W2);
    const float* bias = (mat == 0) ? b0p : (mat == 1 ? b1p : b2p);
    const int nw = n0 & 255;

    const int wid  = tid >> 5;
    const int lane = tid & 31;
    const int WM = (wid & 1) * 64;    // warp m base
    const int WN = (wid >> 1) * 32;   // warp n base

    // loader coords: 2 passes x 256 threads x float4 per 128x16 tile
    const int lrow0 = tid >> 2;            // pass0 row 0..63
    const int lc    = (tid & 3) << 2;      // col 0,4,8,12

    float acc[4][4][4];
    #pragma unroll
    for (int i = 0; i < 4; i++)
        #pragma unroll
        for (int j = 0; j < 4; j++)
            #pragma unroll
            for (int e = 0; e < 4; e++) acc[i][j][e] = 0.f;

    // prefetch stage 0
    float4 pA[2], pB[2];
    {
        pA[0] = *(const float4*)(A + (size_t)(m0 + lrow0) * 256 + lc);
        pA[1] = *(const float4*)(A + (size_t)(m0 + lrow0 + 64) * 256 + lc);
        pB[0] = *(const float4*)(W + (size_t)(nw + lrow0) * 256 + lc);
        pB[1] = *(const float4*)(W + (size_t)(nw + lrow0 + 64) * 256 + lc);
    }

    for (int s = 0; s < 256 / BKE; s++) {
        // split + store to smem
        #pragma unroll
        for (int p = 0; p < 2; p++) {
            int r = lrow0 + p * 64;
            float v[4] = { pA[p].x, pA[p].y, pA[p].z, pA[p].w };
            float hi[4], lo[4];
            #pragma unroll
            for (int e = 0; e < 4; e++) {
                hi[e] = __half2float(__float2half_rn(v[e]));
                lo[e] = v[e] - hi[e];
            }
            *(uint2*)&sAhi[r][lc] = make_uint2(packh(hi[0], hi[1]), packh(hi[2], hi[3]));
            *(uint2*)&sAlo[r][lc] = make_uint2(packh(lo[0], lo[1]), packh(lo[2], lo[3]));
            float w[4] = { pB[p].x, pB[p].y, pB[p].z, pB[p].w };
            #pragma unroll
            for (int e = 0; e < 4; e++) {
                hi[e] = __half2float(__float2half_rn(w[e]));
                lo[e] = w[e] - hi[e];
            }
            *(uint2*)&sBhi[r][lc] = make_uint2(packh(hi[0], hi[1]), packh(hi[2], hi[3]));
            *(uint2*)&sBlo[r][lc] = make_uint2(packh(lo[0], lo[1]), packh(lo[2], lo[3]));
        }
        __syncthreads();

        // prefetch next stage
        if (s + 1 < 256 / BKE) {
            int ks = (s + 1) * BKE + lc;
            pA[0] = *(const float4*)(A + (size_t)(m0 + lrow0) * 256 + ks);
            pA[1] = *(const float4*)(A + (size_t)(m0 + lrow0 + 64) * 256 + ks);
            pB[0] = *(const float4*)(W + (size_t)(nw + lrow0) * 256 + ks);
            pB[1] = *(const float4*)(W + (size_t)(nw + lrow0 + 64) * 256 + ks);
        }

        // fragment loads
        uint32_t ah[4][4], al[4][4], bh[2][4], bl[2][4];
        const int am = WM + (lane & 15);
        const int ac = (lane & 16) >> 1;     // 0 or 8
        #pragma unroll
        for (int i = 0; i < 4; i++) {
            ldsm4(ah[i], &sAhi[am + i * 16][ac]);
            ldsm4(al[i], &sAlo[am + i * 16][ac]);
        }
        const int bn = WN + (lane & 7) + ((lane & 16) >> 1);
        const int bc = lane & 8;
        #pragma unroll
        for (int j = 0; j < 2; j++) {
            ldsm4(bh[j], &sBhi[bn + j * 16][bc]);
            ldsm4(bl[j], &sBlo[bn + j * 16][bc]);
        }

        // 3-term mma
        #pragma unroll
        for (int i = 0; i < 4; i++) {
            #pragma unroll
            for (int jj = 0; jj < 4; jj++) {
                const uint32_t* bhp = &bh[jj >> 1][(jj & 1) * 2];
                const uint32_t* blp = &bl[jj >> 1][(jj & 1) * 2];
                mma16816(acc[i][jj], ah[i], bhp);
                mma16816(acc[i][jj], al[i], bhp);
                mma16816(acc[i][jj], ah[i], blp);
            }
        }
        __syncthreads();
    }

    // epilogue: bias + store
    const int cr = lane >> 2;          // 0..7
    const int cc = (lane & 3) * 2;     // 0,2,4,6
    #pragma unroll
    for (int jj = 0; jj < 4; jj++) {
        int colg = n0 + WN + jj * 8 + cc;
        float bv0 = bias[nw + WN + jj * 8 + cc];
        float bv1 = bias[nw + WN + jj * 8 + cc + 1];
        #pragma unroll
        for (int i = 0; i < 4; i++) {
            int r0 = m0 + WM + i * 16 + cr;
            float2 o0 = make_float2(acc[i][jj][0] + bv0, acc[i][jj][1] + bv1);
            float2 o1 = make_float2(acc[i][jj][2] + bv0, acc[i][jj][3] + bv1);
            *(float2*)(C + (size_t)r0 * ldc + colg)       = o0;
            *(float2*)(C + (size_t)(r0 + 8) * ldc + colg) = o1;
        }
    }
}

// ---------------------------------------------------------------------------
// Attention: one block per (b,n); warp w = head w.
// ---------------------------------------------------------------------------
__global__ __launch_bounds__(256) void attn_kernel(
    const float* __restrict__ memk,
    const float* __restrict__ memv,
    const float* __restrict__ alpha,
    const float* __restrict__ QKV,
    float* __restrict__ O)
{
    __shared__ float sQ[HH][TT][33];
    __shared__ float sK[HH][TT][33];
    __shared__ float sV[HH][TT][33];
    __shared__ float sS[HH][TT][13];
    __shared__ float sL[HH][TT][8];

    const int bn   = blockIdx.x;
    const int h    = threadIdx.x >> 5;
    const int lane = threadIdx.x & 31;
    const size_t rb = (size_t)bn * TT * 768;
    const float scale = 0.1767766952966369f;

    #pragma unroll
    for (int t = 0; t < TT; t++) {
        sQ[h][t][lane] = QKV[rb + (size_t)t * 768 +       h * 32 + lane];
        sK[h][t][lane] = QKV[rb + (size_t)t * 768 + 256 + h * 32 + lane];
        sV[h][t][lane] = QKV[rb + (size_t)t * 768 + 512 + h * 32 + lane];
    }
    __syncwarp();

    for (int p = lane; p < 144; p += 32) {
        int t = p / 12, s = p - t * 12;
        if (s <= t) {
            float a = 0.f;
            #pragma unroll
            for (int k = 0; k < 32; k++) a += sQ[h][t][k] * sK[h][s][k];
            sS[h][t][s] = a * scale;
        }
    }
    for (int p = lane; p < 96; p += 32) {
        int t = p >> 3, m = p & 7;
        const float* mk = memk + ((h << 3) + m) * 32;
        float a = 0.f;
        #pragma unroll
        for (int k = 0; k < 32; k++) a += sQ[h][t][k] * mk[k];
        sL[h][t][m] = a * scale;
    }
    __syncwarp();

    if (lane < TT) {
        int t = lane;
        float mx = -1e30f;
        for (int s = 0; s <= t; s++) mx = fmaxf(mx, sS[h][t][s]);
        float sum = 0.f;
        for (int s = 0; s <= t; s++) { float e = __expf(sS[h][t][s] - mx); sS[h][t][s] = e; sum += e; }
        float inv = 1.f / sum;
        for (int s = 0; s <= t; s++) sS[h][t][s] *= inv;

        mx = -1e30f;
        #pragma unroll
        for (int m = 0; m < 8; m++) mx = fmaxf(mx, sL[h][t][m]);
        sum = 0.f;
        #pragma unroll
        for (int m = 0; m < 8; m++) { float e = __expf(sL[h][t][m] - mx); sL[h][t][m] = e; sum += e; }
        inv = 1.f / sum;
        #pragma unroll
        for (int m = 0; m < 8; m++) sL[h][t][m] *= inv;
    }
    __syncwarp();

    const float wl = 1.f / (1.f + __expf(-alpha[0]));
    const float wt = 1.f - wl;

    #pragma unroll
    for (int t = 0; t < TT; t++) {
        float ot = 0.f;
        for (int s = 0; s <= t; s++) ot += sS[h][t][s] * sV[h][s][lane];
        float ol = 0.f;
        #pragma unroll
        for (int m = 0; m < 8; m++) ol += sL[h][t][m] * memv[((h << 3) + m) * 32 + lane];
        O[(size_t)bn * TT * 256 + (size_t)t * 256 + h * 32 + lane] = ot * wt + ol * wl;
    }
}

// ---------------------------------------------------------------------------
// Residual + LayerNorm: one warp per row of 256.
// ---------------------------------------------------------------------------
__global__ __launch_bounds__(256) void ln_kernel(
    const float* __restrict__ Y, const float* __restrict__ X,
    const float* __restrict__ gamma, const float* __restrict__ beta,
    float* __restrict__ out)
{
    int gw   = (blockIdx.x * blockDim.x + threadIdx.x) >> 5;
    int lane = threadIdx.x & 31;
    if (gw >= ROWS) return;
    size_t base = (size_t)gw * 256 + lane * 8;

    float4 y1 = *(const float4*)(Y + base);
    float4 y2 = *(const float4*)(Y + base + 4);
    float4 x1 = *(const float4*)(X + base);
    float4 x2 = *(const float4*)(X + base + 4);
    float hh[8] = { y1.x + x1.x, y1.y + x1.y, y1.z + x1.z, y1.w + x1.w,
                    y2.x + x2.x, y2.y + x2.y, y2.z + x2.z, y2.w + x2.w };

    float s = 0.f, sq = 0.f;
    #pragma unroll
    for (int i = 0; i < 8; i++) { s += hh[i]; sq += hh[i] * hh[i]; }
    #pragma unroll
    for (int off = 16; off; off >>= 1) {
        s  += __shfl_xor_sync(0xFFFFFFFFu, s,  off);
        sq += __shfl_xor_sync(0xFFFFFFFFu, sq, off);
    }
    float mu  = s * (1.f / 256.f);
    float var = sq * (1.f / 256.f) - mu * mu;
    float rs  = rsqrtf(var + 1e-5f);

    float4 g1 = *(const float4*)(gamma + lane * 8);
    float4 g2 = *(const float4*)(gamma + lane * 8 + 4);
    float4 be1 = *(const float4*)(beta + lane * 8);
    float4 be2 = *(const float4*)(beta + lane * 8 + 4);

    float4 o1 = make_float4((hh[0] - mu) * rs * g1.x + be1.x,
                            (hh[1] - mu) * rs * g1.y + be1.y,
                            (hh[2] - mu) * rs * g1.z + be1.z,
                            (hh[3] - mu) * rs * g1.w + be1.w);
    float4 o2 = make_float4((hh[4] - mu) * rs * g2.x + be2.x,
                            (hh[5] - mu) * rs * g2.y + be2.y,
                            (hh[6] - mu) * rs * g2.z + be2.z,
                            (hh[7] - mu) * rs * g2.w + be2.w);
    *(float4*)(out + base)     = o1;
    *(float4*)(out + base + 4) = o2;
}

// ---------------------------------------------------------------------------
extern "C" void kernel_launch(void* const* d_in, const int* in_sizes, int n_in,
                              void* d_out, int out_size)
{
    const float* x     = (const float*)d_in[0];
    const float* Wq    = (const float*)d_in[1];
    const float* bq    = (const float*)d_in[2];
    const float* Wk    = (const float*)d_in[3];
    const float* bk    = (const float*)d_in[4];
    const float* Wv    = (const float*)d_in[5];
    const float* bv    = (const float*)d_in[6];
    const float* memk  = (const float*)d_in[7];
    const float* memv  = (const float*)d_in[8];
    const float* fcw   = (const float*)d_in[9];
    const float* fcb   = (const float*)d_in[10];
    const float* gamma = (const float*)d_in[11];
    const float* beta  = (const float*)d_in[12];
    const float* alpha = (const float*)d_in[13];
    float* out = (float*)d_out;

    float *qkv, *att, *fc;
    cudaGetSymbolAddress((void**)&qkv, g_qkv);
    cudaGetSymbolAddress((void**)&att, g_att);
    cudaGetSymbolAddress((void**)&fc,  g_fc);

    // 1) fused QKV projection (tensor cores, fp16 split x3)
    {
        dim3 grid(768 / BNTILE, ROWS / BM);
        gemm_f16x3<<<grid, 256>>>(x, Wq, Wk, Wv, bq, bk, bv, qkv, 768);
    }
    // 2) attention per (b,n)
    attn_kernel<<<BNTOT, 256>>>(memk, memv, alpha, qkv, att);

    // 3) FC projection
    {
        dim3 grid(256 / BNTILE, ROWS / BM);
        gemm_f16x3<<<grid, 256>>>(att, fcw, fcw, fcw, fcb, fcb, fcb, fc, 256);
    }
    // 4) residual + LayerNorm
    ln_kernel<<<(ROWS * 32 + 255) / 256, 256>>>(fc, x, gamma, beta, out);
}